// round 5
// baseline (speedup 1.0000x reference)
#include <cuda_runtime.h>
#include <cstdint>
#include <cstddef>

// Problem dims
#define UCNT 32
#define BBAT 256
#define DDIM 768
#define KDIM 3072   // P*D = 4*768

// GEMM tiling
#define BM 256
#define BN 64
#define BK 16
#define BKP 20      // padded A tile row (floats) — conflict-free frag reads
#define BNP 72      // padded B tile row (floats)
#define NKT (KDIM / BK)   // 192
#define STAGES 4
#define STAGE_FLOATS (BM * BKP + BK * BNP)   // 6272
#define SMEM_BYTES (STAGES * STAGE_FLOATS * 4)  // 100352

// A pre-converted to tf32 (rna) — device scratch (no runtime alloc allowed)
__device__ float g_Atf[BBAT * KDIM];

__device__ __forceinline__ uint32_t f2tf32(float f) {
    uint32_t r;
    asm("cvt.rna.tf32.f32 %0, %1;" : "=r"(r) : "f"(f));
    return r;
}

// ---------------- A pre-conversion (fp32 -> tf32 rna), done once ----------------
__global__ void coldprompt_convertA(const float* __restrict__ A, float* __restrict__ outA) {
    int i = blockIdx.x * blockDim.x + threadIdx.x;
    if (i < BBAT * KDIM) outA[i] = __uint_as_float(f2tf32(A[i]));
}

// C[u, 0:256, n0:n0+64] = A[256,3072] @ W[u][3072,768] + bias[u]
// A already tf32-rounded; W fed raw (HMMA tf32 truncation).
__global__ __launch_bounds__(256, 2)
void coldprompt_gemm_tf32(const float* __restrict__ W,     // [32, 3072, 768]
                          const float* __restrict__ bias,  // [32, 768]
                          float* __restrict__ out)         // [32*256, 768]
{
    extern __shared__ float smem[];

    const int u    = blockIdx.y;
    const int n0   = blockIdx.x * BN;
    const int tid  = threadIdx.x;
    const int warp = tid >> 5;
    const int lane = tid & 31;
    const int g    = lane >> 2;   // 0..7
    const int tg   = lane & 3;    // 0..3

    const float* Wu = W + (size_t)u * KDIM * DDIM;

    // staging: A tile 256x16 -> one row (4x16B) per thread
    const int aRow = tid;
    // B tile 16x64 -> 256 chunks of 16B, 1 per thread
    const int bRow = tid >> 4;          // 0..15
    const int bCol = (tid & 15) << 2;   // 0,4,...,60

    const uint32_t smemBase = (uint32_t)__cvta_generic_to_shared(smem);
    const float* agBase = g_Atf + (size_t)aRow * KDIM;
    const float* bgBase = Wu + (size_t)bRow * DDIM + n0 + bCol;

    // Issue cp.async for k-tile kt into stage slot; always commits a group.
    auto load_tiles = [&](int kt, int slot) {
        const int kBase = kt * BK;
        const float* ag = agBase + kBase;
        uint32_t as = smemBase + (uint32_t)((slot * STAGE_FLOATS + aRow * BKP) * 4);
        #pragma unroll
        for (int c = 0; c < 4; c++) {
            asm volatile("cp.async.cg.shared.global [%0], [%1], 16;\n"
                         :: "r"(as + c * 16), "l"(ag + c * 4));
        }
        const float* bg = bgBase + (size_t)kBase * DDIM;
        uint32_t bs = smemBase +
            (uint32_t)((slot * STAGE_FLOATS + BM * BKP + bRow * BNP + bCol) * 4);
        asm volatile("cp.async.cg.shared.global [%0], [%1], 16;\n"
                     :: "r"(bs), "l"(bg));
    };

    float acc[2][8][4];
    #pragma unroll
    for (int i = 0; i < 2; i++)
        #pragma unroll
        for (int j = 0; j < 8; j++)
            #pragma unroll
            for (int c = 0; c < 4; c++) acc[i][j][c] = 0.0f;

    // Prologue: fill STAGES-1 slots
    #pragma unroll
    for (int s = 0; s < STAGES - 1; s++) {
        load_tiles(s, s);
        asm volatile("cp.async.commit_group;\n");
    }

    #pragma unroll 1
    for (int kt = 0; kt < NKT; kt++) {
        const int slot = kt & (STAGES - 1);

        // 3 groups pending (kt, kt+1, kt+2); complete group kt.
        asm volatile("cp.async.wait_group %0;\n" :: "n"(STAGES - 2));
        __syncthreads();

        // Refill: overwrites slot (kt-1)%4, finished before the sync above.
        if (kt + STAGES - 1 < NKT)
            load_tiles(kt + STAGES - 1, (kt + STAGES - 1) & (STAGES - 1));
        asm volatile("cp.async.commit_group;\n");   // keep group count uniform

        const float* Asb = smem + slot * STAGE_FLOATS;
        const float* Bsb = Asb + BM * BKP;

        #pragma unroll
        for (int ks = 0; ks < 2; ks++) {
            const int k0 = ks * 8;
            uint32_t aF[2][4];
            #pragma unroll
            for (int mt = 0; mt < 2; mt++) {
                const int mBase = warp * 32 + mt * 16;
                aF[mt][0] = __float_as_uint(Asb[(mBase + g)     * BKP + k0 + tg]);
                aF[mt][1] = __float_as_uint(Asb[(mBase + g + 8) * BKP + k0 + tg]);
                aF[mt][2] = __float_as_uint(Asb[(mBase + g)     * BKP + k0 + tg + 4]);
                aF[mt][3] = __float_as_uint(Asb[(mBase + g + 8) * BKP + k0 + tg + 4]);
            }
            uint32_t bF[8][2];
            #pragma unroll
            for (int nt = 0; nt < 8; nt++) {
                const int nBase = nt * 8;
                bF[nt][0] = __float_as_uint(Bsb[(k0 + tg)     * BNP + nBase + g]);
                bF[nt][1] = __float_as_uint(Bsb[(k0 + tg + 4) * BNP + nBase + g]);
            }
            #pragma unroll
            for (int mt = 0; mt < 2; mt++)
                #pragma unroll
                for (int nt = 0; nt < 8; nt++) {
                    asm volatile(
                        "mma.sync.aligned.m16n8k8.row.col.f32.tf32.tf32.f32 "
                        "{%0,%1,%2,%3}, {%4,%5,%6,%7}, {%8,%9}, {%0,%1,%2,%3};\n"
                        : "+f"(acc[mt][nt][0]), "+f"(acc[mt][nt][1]),
                          "+f"(acc[mt][nt][2]), "+f"(acc[mt][nt][3])
                        : "r"(aF[mt][0]), "r"(aF[mt][1]), "r"(aF[mt][2]), "r"(aF[mt][3]),
                          "r"(bF[nt][0]), "r"(bF[nt][1]));
                }
        }
    }

    // Epilogue: add bias, write fp32
    const float* bu  = bias + u * DDIM + n0;
    float* outU = out + (size_t)u * BBAT * DDIM + n0;
    #pragma unroll
    for (int mt = 0; mt < 2; mt++) {
        const int mBase = warp * 32 + mt * 16;
        #pragma unroll
        for (int nt = 0; nt < 8; nt++) {
            const int col0 = nt * 8 + 2 * tg;
            const float bv0 = bu[col0];
            const float bv1 = bu[col0 + 1];
            outU[(size_t)(mBase + g)     * DDIM + col0]     = acc[mt][nt][0] + bv0;
            outU[(size_t)(mBase + g)     * DDIM + col0 + 1] = acc[mt][nt][1] + bv1;
            outU[(size_t)(mBase + g + 8) * DDIM + col0]     = acc[mt][nt][2] + bv0;
            outU[(size_t)(mBase + g + 8) * DDIM + col0 + 1] = acc[mt][nt][3] + bv1;
        }
    }
}

// mean_emb[b, d] = mean over P=4 of weight[b, p, d] — float4 vectorized
__global__ void coldprompt_mean(const float4* __restrict__ w, float4* __restrict__ out)
{
    const int i = blockIdx.x * blockDim.x + threadIdx.x;   // float4 index
    const int N4 = BBAT * DDIM / 4;
    if (i < N4) {
        const int D4 = DDIM / 4;
        const int b = i / D4;
        const int d = i % D4;
        const float4* p = w + (size_t)b * 4 * D4 + d;
        float4 v0 = p[0], v1 = p[D4], v2 = p[2 * D4], v3 = p[3 * D4];
        float4 r;
        r.x = 0.25f * (v0.x + v1.x + v2.x + v3.x);
        r.y = 0.25f * (v0.y + v1.y + v2.y + v3.y);
        r.z = 0.25f * (v0.z + v1.z + v2.z + v3.z);
        r.w = 0.25f * (v0.w + v1.w + v2.w + v3.w);
        out[i] = r;
    }
}

extern "C" void kernel_launch(void* const* d_in, const int* in_sizes, int n_in,
                              void* d_out, int out_size)
{
    const float* weight = nullptr;   // [256, 4, 768]
    const float* W      = nullptr;   // [32, 3072, 768]
    const float* bias   = nullptr;   // [32, 768]
    for (int i = 0; i < n_in; i++) {
        if      (in_sizes[i] == BBAT * 4 * DDIM)    weight = (const float*)d_in[i];
        else if (in_sizes[i] == UCNT * KDIM * DDIM) W      = (const float*)d_in[i];
        else if (in_sizes[i] == UCNT * DDIM)        bias   = (const float*)d_in[i];
    }
    float* out = (float*)d_out;

    // 1) Convert A (prompt_emb) to tf32-rna once
    float* atf = nullptr;
    cudaGetSymbolAddress((void**)&atf, g_Atf);
    const int aElems = BBAT * KDIM;
    coldprompt_convertA<<<(aElems + 255) / 256, 256>>>(weight, atf);

    // 2) GEMM
    cudaFuncSetAttribute(coldprompt_gemm_tf32,
                         cudaFuncAttributeMaxDynamicSharedMemorySize, SMEM_BYTES);
    dim3 grid(DDIM / BN, UCNT);   // (12, 32)
    coldprompt_gemm_tf32<<<grid, 256, SMEM_BYTES>>>(W, bias, out);

    // 3) mean_emb tail
    const int mean4 = BBAT * DDIM / 4;
    coldprompt_mean<<<(mean4 + 255) / 256, 256>>>(
        (const float4*)weight, (float4*)(out + (size_t)UCNT * BBAT * DDIM));

    (void)out_size;
}

// round 6
// speedup vs baseline: 1.9588x; 1.9588x over previous
#include <cuda_runtime.h>
#include <cuda_fp16.h>
#include <cstdint>
#include <cstddef>

// Problem dims
#define UCNT 32
#define BBAT 256
#define DDIM 768
#define KDIM 3072   // P*D

// GEMM tiling
#define BM 256
#define BN 64
#define BK 32
#define NKT (KDIM / BK)   // 96
#define ROWB 80           // bytes per smem row: 32 fp16 (64B) + 16B pad (conflict-free)
#define A_STAGE_B (BM * ROWB)            // 20480
#define B_STAGE_B (BN * ROWB)            // 5120
#define STAGE_B   (A_STAGE_B + B_STAGE_B) // 25600
#define SMEM_BYTES (2 * STAGE_B)          // 51200

// A pre-converted to fp16 (rn) — device scratch (no runtime alloc allowed)
__device__ __half g_Ah[BBAT * KDIM];

// ---------------- helpers ----------------
__device__ __forceinline__ void ldsm_x4(uint32_t* r, uint32_t addr) {
    asm volatile("ldmatrix.sync.aligned.m8n8.x4.shared.b16 {%0,%1,%2,%3}, [%4];"
                 : "=r"(r[0]), "=r"(r[1]), "=r"(r[2]), "=r"(r[3]) : "r"(addr));
}
__device__ __forceinline__ void mma_f16(float* d, const uint32_t* a, uint32_t b0, uint32_t b1) {
    asm volatile(
        "mma.sync.aligned.m16n8k16.row.col.f32.f16.f16.f32 "
        "{%0,%1,%2,%3}, {%4,%5,%6,%7}, {%8,%9}, {%0,%1,%2,%3};\n"
        : "+f"(d[0]), "+f"(d[1]), "+f"(d[2]), "+f"(d[3])
        : "r"(a[0]), "r"(a[1]), "r"(a[2]), "r"(a[3]), "r"(b0), "r"(b1));
}
__device__ __forceinline__ uint32_t pack_h2(float lo, float hi) {
    __half2 h = __floats2half2_rn(lo, hi);
    return *reinterpret_cast<uint32_t*>(&h);
}

// ---------------- A pre-conversion (fp32 -> fp16 rn), once per launch ----------------
__global__ void coldprompt_convertA(const float4* __restrict__ A, uint2* __restrict__ outA) {
    int i = blockIdx.x * blockDim.x + threadIdx.x;   // float4 index
    if (i < BBAT * KDIM / 4) {
        float4 v = A[i];
        uint2 o;
        o.x = pack_h2(v.x, v.y);
        o.y = pack_h2(v.z, v.w);
        outA[i] = o;
    }
}

// C[u, 0:256, n0:n0+64] = A[256,3072] @ W[u][3072,768] + bias[u]
__global__ __launch_bounds__(256, 2)
void coldprompt_gemm_f16(const float* __restrict__ W,     // [32, 3072, 768]
                         const float* __restrict__ bias,  // [32, 768]
                         float* __restrict__ out)         // [32*256, 768]
{
    extern __shared__ char smem[];
    const uint32_t sb = (uint32_t)__cvta_generic_to_shared(smem);

    const int u    = blockIdx.y;
    const int n0   = blockIdx.x * BN;
    const int tid  = threadIdx.x;
    const int warp = tid >> 5;
    const int lane = tid & 31;
    const int g    = lane >> 2;   // 0..7
    const int tg   = lane & 3;    // 0..3

    // ldmatrix per-lane offsets (byte offsets within a tile region)
    const uint32_t aLane = (uint32_t)(((lane & 7) + ((lane >> 3) & 1) * 8) * ROWB + (lane >> 4) * 16);
    const uint32_t bLane = (uint32_t)(((lane & 7) + (lane >> 4) * 8) * ROWB + ((lane >> 3) & 1) * 16);

    // A staging: thread -> one row; 4x 16B cp.async per ktile (already fp16)
    const __half* agBase = g_Ah + (size_t)tid * KDIM;
    const uint32_t aDstRow = (uint32_t)(tid * ROWB);

    // B staging: thread -> (kp, n); 8 LDG.32 + cvt + 4 STS.32 per ktile
    const int n_  = tid & 63;
    const int kp  = tid >> 6;   // 0..3
    const float* bgBase = W + (size_t)u * KDIM * DDIM + n0 + n_;

    float bw0[4], bw1[4];       // prefetched W values for next tile
    auto ldgB = [&](int kt) {
        const size_t kBase = (size_t)kt * BK;
        #pragma unroll
        for (int j = 0; j < 4; j++) {
            const size_t k = kBase + 8 * j + 2 * kp;
            bw0[j] = bgBase[k * DDIM];
            bw1[j] = bgBase[(k + 1) * DDIM];
        }
    };
    auto stsB = [&](uint32_t stageBase) {
        const uint32_t bBase = stageBase + A_STAGE_B + (uint32_t)(n_ * ROWB);
        #pragma unroll
        for (int j = 0; j < 4; j++) {
            uint32_t v = pack_h2(bw0[j], bw1[j]);
            asm volatile("st.shared.b32 [%0], %1;"
                         :: "r"(bBase + (uint32_t)((4 * j + kp) * 4)), "r"(v) : "memory");
        }
    };
    auto cpA = [&](int kt, uint32_t stageBase) {
        const __half* src = agBase + (size_t)kt * BK;
        const uint32_t dst = stageBase + aDstRow;
        #pragma unroll
        for (int c = 0; c < 4; c++) {
            asm volatile("cp.async.cg.shared.global [%0], [%1], 16;"
                         :: "r"(dst + c * 16), "l"(src + c * 8));
        }
        asm volatile("cp.async.commit_group;");
    };

    float acc[2][8][4];
    #pragma unroll
    for (int i = 0; i < 2; i++)
        #pragma unroll
        for (int j = 0; j < 8; j++)
            #pragma unroll
            for (int c = 0; c < 4; c++) acc[i][j][c] = 0.0f;

    const uint32_t s0 = sb, s1 = sb + STAGE_B;

    // Prologue
    ldgB(0);
    cpA(0, s0);
    stsB(s0);
    ldgB(1);
    cpA(1, s1);
    asm volatile("cp.async.wait_group 1;");
    __syncthreads();

    #pragma unroll 1
    for (int kt = 0; kt < NKT; kt++) {
        const uint32_t cur = (kt & 1) ? s1 : s0;
        const uint32_t nxt = (kt & 1) ? s0 : s1;

        if (kt + 1 < NKT) {
            stsB(nxt);                      // B(kt+1) -> other stage (A region disjoint)
            if (kt + 2 < NKT) ldgB(kt + 2); // prefetch W for tile kt+2
        }

        // Compute on cur: 2 k16 steps
        #pragma unroll
        for (int ks = 0; ks < 2; ks++) {
            uint32_t aF[2][4];
            ldsm_x4(aF[0], cur + (uint32_t)((warp * 32) * ROWB + ks * 32) + aLane);
            ldsm_x4(aF[1], cur + (uint32_t)((warp * 32 + 16) * ROWB + ks * 32) + aLane);
            uint32_t bF[4][4];
            #pragma unroll
            for (int p = 0; p < 4; p++)
                ldsm_x4(bF[p], cur + A_STAGE_B + (uint32_t)((p * 16) * ROWB + ks * 32) + bLane);
            #pragma unroll
            for (int mt = 0; mt < 2; mt++)
                #pragma unroll
                for (int nt = 0; nt < 8; nt++)
                    mma_f16(acc[mt][nt], aF[mt], bF[nt >> 1][2 * (nt & 1)], bF[nt >> 1][2 * (nt & 1) + 1]);
        }

        if (kt + 1 < NKT) {
            asm volatile("cp.async.wait_group 0;");   // A(kt+1) landed
            __syncthreads();                          // B(kt+1) visible; cur free
            if (kt + 2 < NKT) cpA(kt + 2, cur);
        }
    }

    // Epilogue: add bias, write fp32
    const float* bu  = bias + u * DDIM + n0;
    float* outU = out + (size_t)u * BBAT * DDIM + n0;
    #pragma unroll
    for (int mt = 0; mt < 2; mt++) {
        const int mBase = warp * 32 + mt * 16;
        #pragma unroll
        for (int nt = 0; nt < 8; nt++) {
            const int col0 = nt * 8 + 2 * tg;
            const float bv0 = bu[col0];
            const float bv1 = bu[col0 + 1];
            outU[(size_t)(mBase + g)     * DDIM + col0]     = acc[mt][nt][0] + bv0;
            outU[(size_t)(mBase + g)     * DDIM + col0 + 1] = acc[mt][nt][1] + bv1;
            outU[(size_t)(mBase + g + 8) * DDIM + col0]     = acc[mt][nt][2] + bv0;
            outU[(size_t)(mBase + g + 8) * DDIM + col0 + 1] = acc[mt][nt][3] + bv1;
        }
    }
}

// mean_emb[b, d] = mean over P=4 of weight[b, p, d] — float4 vectorized
__global__ void coldprompt_mean(const float4* __restrict__ w, float4* __restrict__ out)
{
    const int i = blockIdx.x * blockDim.x + threadIdx.x;
    const int N4 = BBAT * DDIM / 4;
    if (i < N4) {
        const int D4 = DDIM / 4;
        const int b = i / D4;
        const int d = i % D4;
        const float4* p = w + (size_t)b * 4 * D4 + d;
        float4 v0 = p[0], v1 = p[D4], v2 = p[2 * D4], v3 = p[3 * D4];
        float4 r;
        r.x = 0.25f * (v0.x + v1.x + v2.x + v3.x);
        r.y = 0.25f * (v0.y + v1.y + v2.y + v3.y);
        r.z = 0.25f * (v0.z + v1.z + v2.z + v3.z);
        r.w = 0.25f * (v0.w + v1.w + v2.w + v3.w);
        out[i] = r;
    }
}

extern "C" void kernel_launch(void* const* d_in, const int* in_sizes, int n_in,
                              void* d_out, int out_size)
{
    const float* weight = nullptr;   // [256, 4, 768]
    const float* W      = nullptr;   // [32, 3072, 768]
    const float* bias   = nullptr;   // [32, 768]
    for (int i = 0; i < n_in; i++) {
        if      (in_sizes[i] == BBAT * 4 * DDIM)    weight = (const float*)d_in[i];
        else if (in_sizes[i] == UCNT * KDIM * DDIM) W      = (const float*)d_in[i];
        else if (in_sizes[i] == UCNT * DDIM)        bias   = (const float*)d_in[i];
    }
    float* out = (float*)d_out;

    // 1) Convert A (prompt_emb) to fp16 once
    __half* ah = nullptr;
    cudaGetSymbolAddress((void**)&ah, g_Ah);
    const int a4 = BBAT * KDIM / 4;
    coldprompt_convertA<<<(a4 + 255) / 256, 256>>>((const float4*)weight, (uint2*)ah);

    // 2) GEMM (fp16 MMA, fp32 accumulate)
    cudaFuncSetAttribute(coldprompt_gemm_f16,
                         cudaFuncAttributeMaxDynamicSharedMemorySize, SMEM_BYTES);
    dim3 grid(DDIM / BN, UCNT);   // (12, 32)
    coldprompt_gemm_f16<<<grid, 256, SMEM_BYTES>>>(W, bias, out);

    // 3) mean_emb tail
    const int mean4 = BBAT * DDIM / 4;
    coldprompt_mean<<<(mean4 + 255) / 256, 256>>>(
        (const float4*)weight, (float4*)(out + (size_t)UCNT * BBAT * DDIM));

    (void)out_size;
}